// round 7
// baseline (speedup 1.0000x reference)
#include <cuda_runtime.h>
#include <cuda_bf16.h>

// Submanifold sparse conv, 2 layers, C=64, KV=27, N=200000, grid 128^3, B=2.
// Per-offset pair buckets. Center offset (k=13) covers every output row
// exactly once -> plain-store pass (no zeroing needed); other 26 offsets
// accumulate with red.global.add.v4.f32. Packed f32x2 FFMA2 math,
// 8 pairs x 4 out-channels per thread (1.5 smem B/FMA).

#define N_VOX   200000
#define C_CH    64
#define KV_     27
#define DD      128
#define BATCH   2
#define GRID_CELLS (BATCH * DD * DD * DD)

#define CAP_NC     16384
#define CH_CENTER  1563                     // ceil(200000/128)
#define CH_NC      128                      // ceil(CAP_NC/128)
#define TOT_ROWS   (N_VOX + 26 * CAP_NC)
#define REST_BLOCKS (26 * CH_NC)

__device__ int   g_grid[GRID_CELLS];
__device__ int   g_cnt[KV_];
__device__ int   g_pin[TOT_ROWS];
__device__ int   g_pout[TOT_ROWS];
__device__ float g_mid[(size_t)N_VOX * C_CH];

__host__ __device__ __forceinline__ int bucket_base(int k) {
    if (k == 13) return 0;
    int j = (k < 13) ? k : k - 1;
    return N_VOX + j * CAP_NC;
}

// --------------------------------------------- init: grid=-1, counters=0
__global__ void init_kernel() {
    int tid0 = blockIdx.x * blockDim.x + threadIdx.x;
    int stride = gridDim.x * blockDim.x;
    int4* g4 = (int4*)g_grid;
    const int ng4 = GRID_CELLS / 4;
    int4 mone = make_int4(-1, -1, -1, -1);
    for (int i = tid0; i < ng4; i += stride) g4[i] = mone;
    if (blockIdx.x == 0 && threadIdx.x < KV_) g_cnt[threadIdx.x] = 0;
}

// ------------------------------------------------------------------- scatter
// Reference .at[flat].set(arange): last-index-wins = max on duplicates.
__global__ void scatter_kernel(const int* __restrict__ coors) {
    int i = blockIdx.x * blockDim.x + threadIdx.x;
    if (i >= N_VOX) return;
    int4 c = ((const int4*)coors)[i];
    int flat = ((c.x * DD + c.y) * DD + c.z) * DD + c.w;
    atomicMax(&g_grid[flat], i);
}

// -------------------------------------- fused rulebook build + k-compaction
__global__ void build_kernel(const int* __restrict__ coors) {
    int n    = blockIdx.x * blockDim.x + threadIdx.x;
    int lane = threadIdx.x & 31;
    bool live = (n < N_VOX);
    int4 c = ((const int4*)coors)[live ? n : (N_VOX - 1)];
    int base = c.x * DD * DD * DD;

    int k = 0;
    #pragma unroll
    for (int dz = -1; dz <= 1; dz++)
    #pragma unroll
    for (int dy = -1; dy <= 1; dy++)
    #pragma unroll
    for (int dx = -1; dx <= 1; dx++) {
        int nz = c.y + dz, ny = c.z + dy, nx = c.w + dx;
        int idx = -1;
        if (live && (unsigned)nz < DD && (unsigned)ny < DD && (unsigned)nx < DD)
            idx = __ldg(&g_grid[base + (nz * DD + ny) * DD + nx]);
        bool valid = (idx >= 0);
        unsigned mask = __ballot_sync(0xffffffffu, valid);
        if (mask) {
            int leader = __ffs(mask) - 1;
            int wbase = 0;
            if (lane == leader) wbase = atomicAdd(&g_cnt[k], __popc(mask));
            wbase = __shfl_sync(0xffffffffu, wbase, leader);
            if (valid) {
                int p = wbase + __popc(mask & ((1u << lane) - 1u));
                int cap = (k == 13) ? N_VOX : CAP_NC;
                if (p < cap) {
                    int bb = bucket_base(k);
                    g_pin[bb + p]  = idx;
                    g_pout[bb + p] = n;
                }
            }
        }
        k++;
    }
}

// ----------------------------------------------- packed f32x2 helpers
typedef unsigned long long u64t;

__device__ __forceinline__ u64t pack2(float s) {
    u64t r;
    asm("mov.b64 %0, {%1, %1};" : "=l"(r) : "f"(s));
    return r;
}
__device__ __forceinline__ void ffma2(u64t& d, u64t a, u64t b) {
    asm("fma.rn.f32x2 %0, %1, %2, %0;" : "+l"(d) : "l"(a), "l"(b));
}
__device__ __forceinline__ void red_v4(float* ptr, u64t lo, u64t hi) {
    float x, y, z, w;
    asm("mov.b64 {%0, %1}, %2;" : "=f"(x), "=f"(y) : "l"(lo));
    asm("mov.b64 {%0, %1}, %2;" : "=f"(z), "=f"(w) : "l"(hi));
    asm volatile("red.global.add.v4.f32 [%0], {%1, %2, %3, %4};"
                 :: "l"(ptr), "f"(x), "f"(y), "f"(z), "f"(w)
                 : "memory");
}
__device__ __forceinline__ void st_v4(float* ptr, u64t lo, u64t hi) {
    float x, y, z, w;
    asm("mov.b64 {%0, %1}, %2;" : "=f"(x), "=f"(y) : "l"(lo));
    asm("mov.b64 {%0, %1}, %2;" : "=f"(z), "=f"(w) : "l"(hi));
    asm volatile("st.global.v4.f32 [%0], {%1, %2, %3, %4};"
                 :: "l"(ptr), "f"(x), "f"(y), "f"(z), "f"(w)
                 : "memory");
}

// --------------------------------------------------- gather-GEMM per (k,chunk)
// Block: 256 thr, 128 pairs of one offset k. W[k] staged row-major [c][o]
// (16KB), features gathered (32KB). Warp group = 16 pairs: sub = lane>>4
// picks 8 pairs, oc4 = lane&15 picks 4 out channels. Per 4-channel step:
// 12 LDS.128 per thread for 128 FMA (1.5 B/FMA), FFMA2 math.
// CENTER: k=13, every out row exactly once -> plain st.global.v4 (defines
// the row; removes output zeroing). Otherwise red.global.add.v4.
template<bool CENTER>
__global__ __launch_bounds__(256, 2)
void gemm_kernel(const float* __restrict__ fin,
                 const float* __restrict__ Wall,
                 float* __restrict__ fout)
{
    __shared__ float ws[C_CH * C_CH];    // 16 KB
    __shared__ float fs[128 * C_CH];     // 32 KB
    __shared__ int   spo[128];

    int k, chunk;
    if (CENTER) { k = 13; chunk = blockIdx.x; }
    else {
        int j = blockIdx.x >> 7;
        chunk = blockIdx.x & (CH_NC - 1);
        k = (j < 13) ? j : j + 1;
    }
    int mk = g_cnt[k];
    if (!CENTER && mk > CAP_NC) mk = CAP_NC;
    int p0blk = chunk * 128;
    if (p0blk >= mk) return;
    int rem = min(128, mk - p0blk);
    int rowbase = bucket_base(k) + p0blk;

    const int tid  = threadIdx.x;
    const int lane = tid & 31;
    const int warp = tid >> 5;

    {
        const float4* wsrc = (const float4*)(Wall + k * 4096);
        float4* wdst = (float4*)ws;
        #pragma unroll
        for (int i = 0; i < 4; i++) wdst[tid + i * 256] = wsrc[tid + i * 256];
    }
    if (tid < 128 && tid < rem) spo[tid] = __ldg(&g_pout[rowbase + tid]);
    {
        const float4* fin4 = (const float4*)fin;
        float4* fs4 = (float4*)fs;
        for (int r = tid >> 4; r < rem; r += 16)
            fs4[r * 16 + (tid & 15)] =
                fin4[(size_t)__ldg(&g_pin[rowbase + r]) * 16 + (tid & 15)];
    }
    __syncthreads();

    const float4*     fsv = (const float4*)fs;
    const ulonglong2* ws8 = (const ulonglong2*)ws;  // [c][oc4]: .x=ch01 .y=ch23
    const int sub = lane >> 4;
    const int oc4 = lane & 15;

    const int ngroups = (rem + 15) >> 4;
    for (int g = warp; g < ngroups; g += 8) {
        const int pb = g * 16 + sub * 8;
        int q[8];
        #pragma unroll
        for (int p = 0; p < 8; p++) q[p] = min(pb + p, rem - 1);

        u64t al[8], ah[8];
        #pragma unroll
        for (int p = 0; p < 8; p++) { al[p] = 0; ah[p] = 0; }

        #pragma unroll 4
        for (int c4 = 0; c4 < 16; c4++) {
            ulonglong2 w0 = ws8[(4 * c4 + 0) * 16 + oc4];
            ulonglong2 w1 = ws8[(4 * c4 + 1) * 16 + oc4];
            ulonglong2 w2 = ws8[(4 * c4 + 2) * 16 + oc4];
            ulonglong2 w3 = ws8[(4 * c4 + 3) * 16 + oc4];
            #pragma unroll
            for (int p = 0; p < 8; p++) {
                float4 f = fsv[q[p] * 16 + c4];
                u64t s;
                s = pack2(f.x); ffma2(al[p], s, w0.x); ffma2(ah[p], s, w0.y);
                s = pack2(f.y); ffma2(al[p], s, w1.x); ffma2(ah[p], s, w1.y);
                s = pack2(f.z); ffma2(al[p], s, w2.x); ffma2(ah[p], s, w2.y);
                s = pack2(f.w); ffma2(al[p], s, w3.x); ffma2(ah[p], s, w3.y);
            }
        }

        #pragma unroll
        for (int p = 0; p < 8; p++) {
            if (pb + p < rem) {
                float* dst = fout + (size_t)spo[pb + p] * C_CH + oc4 * 4;
                if (CENTER) st_v4(dst, al[p], ah[p]);
                else        red_v4(dst, al[p], ah[p]);
            }
        }
    }
}

// -------------------------------------------------------------------- launch
extern "C" void kernel_launch(void* const* d_in, const int* in_sizes, int n_in,
                              void* d_out, int out_size)
{
    const float* feats = (const float*)d_in[0];
    const int*   coors = (const int*)d_in[1];
    const float* W0    = (const float*)d_in[2];
    const float* W1    = (const float*)d_in[3];
    float*       out   = (float*)d_out;

    float* mid;
    cudaGetSymbolAddress((void**)&mid, g_mid);

    init_kernel<<<1024, 256>>>();
    scatter_kernel<<<(N_VOX + 255) / 256, 256>>>(coors);
    build_kernel<<<(N_VOX + 255) / 256, 256>>>(coors);

    // layer 0: center pass defines rows, rest accumulates (same stream order)
    gemm_kernel<true ><<<CH_CENTER,  256>>>(feats, W0, mid);
    gemm_kernel<false><<<REST_BLOCKS, 256>>>(feats, W0, mid);

    // layer 1
    gemm_kernel<true ><<<CH_CENTER,  256>>>(mid, W1, out);
    gemm_kernel<false><<<REST_BLOCKS, 256>>>(mid, W1, out);
}